// round 2
// baseline (speedup 1.0000x reference)
#include <cuda_runtime.h>
#include <math.h>

typedef unsigned long long u64;

#define NB   4096
#define NL   50
#define NT   64
#define NF   3
#define NH   20
#define NG   80          // 4*NH
#define NO   16
#define NSEQ (NB*NL)     // 204800
#define NPAIR (NSEQ/2)   // 102400
#define LSTM_TPB 64      // threads per CTA in LSTM kernel

// ---------------- device scratch (static; no cudaMalloc anywhere) --------------
__device__ int   g_hist[64];
__device__ int   g_off[64];
__device__ int   g_order[NSEQ];
__device__ float g_summ[(size_t)NSEQ * NO];   // 13.1 MB

// ---------------- packed f32x2 helpers ----------------------------------------
__device__ __forceinline__ u64 f2pack(float lo, float hi) {
    u64 r;
    asm("mov.b64 %0, {%1, %2};" : "=l"(r) : "f"(lo), "f"(hi));
    return r;
}
__device__ __forceinline__ void f2unpack(u64 v, float& lo, float& hi) {
    asm("mov.b64 {%0, %1}, %2;" : "=f"(lo), "=f"(hi) : "l"(v));
}
__device__ __forceinline__ u64 ffma2(u64 a, u64 b, u64 c) {
    u64 d;
    asm("fma.rn.f32x2 %0, %1, %2, %3;" : "=l"(d) : "l"(a), "l"(b), "l"(c));
    return d;
}

// fast sigmoid / tanh: MUFU.EX2 + MUFU.RCP (~1e-6 rel err, safe at 1e-3 tol)
__device__ __forceinline__ float fsig(float v) {
    return __fdividef(1.0f, 1.0f + __expf(-v));
}
__device__ __forceinline__ float ftanh(float v) {
    return __fdividef(2.0f, 1.0f + __expf(-2.0f * v)) - 1.0f;
}

// ---------------- counting sort by length --------------------------------------
__global__ void k_zero() {
    if (threadIdx.x < 64) g_hist[threadIdx.x] = 0;
}
__global__ void k_hist(const int* __restrict__ lengths) {
    int i = blockIdx.x * 256 + threadIdx.x;
    if (i < NSEQ) {
        int l = lengths[i];
        l = min(max(l, 0), 63);
        atomicAdd(&g_hist[l], 1);
    }
}
__global__ void k_scan() {
    if (threadIdx.x == 0) {
        int acc = 0;
        #pragma unroll
        for (int i = 0; i < 64; ++i) { int v = g_hist[i]; g_off[i] = acc; acc += v; }
    }
}
__global__ void k_scatter(const int* __restrict__ lengths) {
    int i = blockIdx.x * 256 + threadIdx.x;
    if (i < NSEQ) {
        int l = lengths[i];
        l = min(max(l, 0), 63);
        int p = atomicAdd(&g_off[l], 1);
        g_order[p] = i;
    }
}

// ---------------- LSTM: 2 seqs/thread, f32x2, named h regs, c in shared --------
// macro: accumulate dot(h, row) into acc; row = pointer to 20 duplicated-pair u64
#define ACC_ROW(acc, rowptr) do {                                              \
    const ulonglong2* wp_ = (const ulonglong2*)(rowptr);                       \
    ulonglong2 w_;                                                             \
    w_ = wp_[0]; acc = ffma2(hh0,  w_.x, acc); acc = ffma2(hh1,  w_.y, acc);   \
    w_ = wp_[1]; acc = ffma2(hh2,  w_.x, acc); acc = ffma2(hh3,  w_.y, acc);   \
    w_ = wp_[2]; acc = ffma2(hh4,  w_.x, acc); acc = ffma2(hh5,  w_.y, acc);   \
    w_ = wp_[3]; acc = ffma2(hh6,  w_.x, acc); acc = ffma2(hh7,  w_.y, acc);   \
    w_ = wp_[4]; acc = ffma2(hh8,  w_.x, acc); acc = ffma2(hh9,  w_.y, acc);   \
    w_ = wp_[5]; acc = ffma2(hh10, w_.x, acc); acc = ffma2(hh11, w_.y, acc);   \
    w_ = wp_[6]; acc = ffma2(hh12, w_.x, acc); acc = ffma2(hh13, w_.y, acc);   \
    w_ = wp_[7]; acc = ffma2(hh14, w_.x, acc); acc = ffma2(hh15, w_.y, acc);   \
    w_ = wp_[8]; acc = ffma2(hh16, w_.x, acc); acc = ffma2(hh17, w_.y, acc);   \
    w_ = wp_[9]; acc = ffma2(hh18, w_.x, acc); acc = ffma2(hh19, w_.y, acc);   \
} while (0)

#define XPROJ(acc, rowidx) do {                                                \
    const u64* xp_ = sWih + (rowidx) * 4;                                      \
    acc = ffma2(x0,  xp_[0], acc);                                             \
    acc = ffma2(x1,  xp_[1], acc);                                             \
    acc = ffma2(x2v, xp_[2], acc);                                             \
} while (0)

#define LOADH(k) hh##k = hnbuf[(k) * LSTM_TPB + tid];

__global__ void __launch_bounds__(LSTM_TPB)
k_lstm(const float* __restrict__ x, const int* __restrict__ lengths,
       const float* __restrict__ w_ih, const float* __restrict__ w_hh,
       const float* __restrict__ b_ih, const float* __restrict__ b_hh,
       const float* __restrict__ w_lin, const float* __restrict__ b_lin)
{
    // duplicated-pair weights: each entry = (w, w) for f32x2 broadcast
    __shared__ __align__(16) u64 sWhh[NG * NH];           // 12800 B
    __shared__ __align__(16) u64 sWih[NG * 4];            //  2560 B (F padded 3->4)
    __shared__ __align__(16) u64 sB[NG];                  //   640 B
    __shared__ __align__(16) u64 sWlin[NO * NH];          //  2560 B
    __shared__ u64 sBlin[NO];                             //   128 B
    __shared__ __align__(16) u64 hnbuf[NH * LSTM_TPB];    // 10240 B (h_new staging)
    __shared__ __align__(16) u64 cbuf [NH * LSTM_TPB];    // 10240 B (c state)
    // total: 39168 B static shared

    const int tid = threadIdx.x;

    for (int i = tid; i < NG * NH; i += LSTM_TPB) { float w = w_hh[i]; sWhh[i] = f2pack(w, w); }
    for (int i = tid; i < NG * 4; i += LSTM_TPB) {
        int r = i >> 2, k = i & 3;
        float w = (k < 3) ? w_ih[r * 3 + k] : 0.0f;
        sWih[i] = f2pack(w, w);
    }
    for (int i = tid; i < NG; i += LSTM_TPB) { float w = b_ih[i] + b_hh[i]; sB[i] = f2pack(w, w); }
    for (int i = tid; i < NO * NH; i += LSTM_TPB) { float w = w_lin[i]; sWlin[i] = f2pack(w, w); }
    if (tid < NO) { float w = b_lin[tid]; sBlin[tid] = f2pack(w, w); }
    // init c state
    #pragma unroll
    for (int j = 0; j < NH; ++j) cbuf[j * LSTM_TPB + tid] = 0ull;
    __syncthreads();

    const int pid = blockIdx.x * LSTM_TPB + tid;
    const int i0 = g_order[2 * pid];
    const int i1 = g_order[2 * pid + 1];
    const int len0 = lengths[i0];
    const int len1 = lengths[i1];
    const int tmax = max(len0, len1);

    const float* p0 = x + (size_t)i0 * (NT * NF);
    const float* p1 = x + (size_t)i1 * (NT * NF);

    // h state in 20 NAMED u64 registers (cannot be demoted to local)
    u64 hh0 = 0, hh1 = 0, hh2 = 0, hh3 = 0, hh4 = 0, hh5 = 0, hh6 = 0, hh7 = 0,
        hh8 = 0, hh9 = 0, hh10 = 0, hh11 = 0, hh12 = 0, hh13 = 0, hh14 = 0,
        hh15 = 0, hh16 = 0, hh17 = 0, hh18 = 0, hh19 = 0;

    u64 x0 = 0, x1 = 0, x2v = 0;
    if (tmax > 0) {
        x0  = f2pack(p0[0], p1[0]);
        x1  = f2pack(p0[1], p1[1]);
        x2v = f2pack(p0[2], p1[2]);
    }

    for (int t = 0; t < tmax; ++t) {
        // prefetch next step's x (rows 0..T-1 always exist)
        const int tn = min(t + 1, NT - 1);
        const u64 xn0 = f2pack(p0[tn * 3 + 0], p1[tn * 3 + 0]);
        const u64 xn1 = f2pack(p0[tn * 3 + 1], p1[tn * 3 + 1]);
        const u64 xn2 = f2pack(p0[tn * 3 + 2], p1[tn * 3 + 2]);

        const bool m0 = (t < len0);
        const bool m1 = (t < len1);

        #pragma unroll 1
        for (int j = 0; j < NH; ++j) {
            u64 ai = sB[j], af = sB[j + 20], ag = sB[j + 40], ao = sB[j + 60];

            XPROJ(ai, j);
            XPROJ(af, j + 20);
            XPROJ(ag, j + 40);
            XPROJ(ao, j + 60);

            ACC_ROW(ai, sWhh + (j)      * NH);
            ACC_ROW(af, sWhh + (j + 20) * NH);
            ACC_ROW(ag, sWhh + (j + 40) * NH);
            ACC_ROW(ao, sWhh + (j + 60) * NH);

            float ai0, ai1, af0, af1, ag0, ag1, ao0, ao1, cc0, cc1;
            f2unpack(ai, ai0, ai1);
            f2unpack(af, af0, af1);
            f2unpack(ag, ag0, ag1);
            f2unpack(ao, ao0, ao1);
            f2unpack(cbuf[j * LSTM_TPB + tid], cc0, cc1);

            float cn0 = fsig(af0) * cc0 + fsig(ai0) * ftanh(ag0);
            float hn0 = fsig(ao0) * ftanh(cn0);
            float cn1 = fsig(af1) * cc1 + fsig(ai1) * ftanh(ag1);
            float hn1 = fsig(ao1) * ftanh(cn1);

            cn0 = m0 ? cn0 : cc0;
            cn1 = m1 ? cn1 : cc1;
            cbuf[j * LSTM_TPB + tid] = f2pack(cn0, cn1);

            // h_new staged in shared; masked against previous h (still in regs)
            u64 hold;
            switch (j) {   // compile-time resolved after unroll? j runtime -> use shared copy
                default: hold = 0ull;
            }
            (void)hold;
            // mask using previous h value read from hnbuf is wrong on t=0; instead
            // store candidate and fix mask by re-selecting from current regs below.
            hnbuf[j * LSTM_TPB + tid] = f2pack(hn0, hn1);
        }

        // commit h: h_new if masked-in, else keep old (old is in named regs)
        {
            u64 v; float a, b, oa, ob;
            #define COMMITH(k)                                                  \
                v = hnbuf[(k) * LSTM_TPB + tid];                                \
                f2unpack(v, a, b);                                              \
                f2unpack(hh##k, oa, ob);                                        \
                a = m0 ? a : oa;                                                \
                b = m1 ? b : ob;                                                \
                hh##k = f2pack(a, b);
            COMMITH(0)  COMMITH(1)  COMMITH(2)  COMMITH(3)  COMMITH(4)
            COMMITH(5)  COMMITH(6)  COMMITH(7)  COMMITH(8)  COMMITH(9)
            COMMITH(10) COMMITH(11) COMMITH(12) COMMITH(13) COMMITH(14)
            COMMITH(15) COMMITH(16) COMMITH(17) COMMITH(18) COMMITH(19)
            #undef COMMITH
        }

        x0 = xn0; x1 = xn1; x2v = xn2;
    }

    // layer summary: sigmoid(h @ w_lin^T + b_lin); zero when len == 0
    #pragma unroll 1
    for (int o = 0; o < NO; ++o) {
        u64 s = sBlin[o];
        ACC_ROW(s, sWlin + o * NH);
        float s0, s1;
        f2unpack(s, s0, s1);
        g_summ[(size_t)i0 * NO + o] = (len0 > 0) ? fsig(s0) : 0.0f;
        g_summ[(size_t)i1 * NO + o] = (len1 > 0) ? fsig(s1) : 0.0f;
    }
}

// ---------------- conv + FC kernel: one CTA per batch element -------------------
#define C1OUT 46
#define C2OUT 22
#define C3OUT 19

__global__ void __launch_bounds__(128)
k_conv(const float* __restrict__ c1_w, const float* __restrict__ c1_b,
       const float* __restrict__ c2_w, const float* __restrict__ c2_b,
       const float* __restrict__ c3_w, const float* __restrict__ c3_b,
       const float* __restrict__ fc1_w, const float* __restrict__ fc1_b,
       const float* __restrict__ fc2_w, const float* __restrict__ fc2_b,
       float* __restrict__ out)
{
    __shared__ float sbuf[10256 + 16];
    float* feat = sbuf;              // [16][50]  : 800
    float* w1   = sbuf + 800;        // 32*16*5   : 2560
    float* y1   = sbuf + 3360;       // [32][46]  : 1472
    float* w2   = sbuf + 4832;       // 32*32*4   : 4096
    float* y2   = sbuf + 8928;       // [32][22]  : 704
    float* y3   = sbuf + 9632;       // [32][19]  : 608
    float* sfc  = sbuf + 10240;      // 16
    float* w3   = sbuf;              // reuse [0,4096) after conv2 (feat/w1/y1 dead)

    const int b   = blockIdx.x;
    const int tid = threadIdx.x;

    for (int i = tid; i < 16 * 50; i += 128) {
        int c = i / 50, l = i % 50;
        feat[c * 50 + l] = g_summ[(size_t)(b * NL + l) * NO + c];
    }
    for (int i = tid; i < 2560; i += 128) w1[i] = c1_w[i];
    for (int i = tid; i < 4096; i += 128) w2[i] = c2_w[i];
    __syncthreads();

    // conv1: 16ch x k5 s1 -> [32][46], relu
    for (int idx = tid; idx < 32 * C1OUT; idx += 128) {
        int o = idx / C1OUT, p = idx % C1OUT;
        float acc = c1_b[o];
        #pragma unroll
        for (int c = 0; c < 16; ++c) {
            const float* f = feat + c * 50 + p;
            const float* w = w1 + (o * 16 + c) * 5;
            #pragma unroll
            for (int k = 0; k < 5; ++k) acc += f[k] * w[k];
        }
        y1[o * C1OUT + p] = fmaxf(acc, 0.0f);
    }
    __syncthreads();

    // conv2: 32ch x k4 s2 -> [32][22], relu
    for (int idx = tid; idx < 32 * C2OUT; idx += 128) {
        int o = idx / C2OUT, p = idx % C2OUT;
        float acc = c2_b[o];
        #pragma unroll
        for (int c = 0; c < 32; ++c) {
            const float* f = y1 + c * C1OUT + 2 * p;
            const float* w = w2 + (o * 32 + c) * 4;
            #pragma unroll
            for (int k = 0; k < 4; ++k) acc += f[k] * w[k];
        }
        y2[o * C2OUT + p] = fmaxf(acc, 0.0f);
    }
    __syncthreads();

    for (int i = tid; i < 4096; i += 128) w3[i] = c3_w[i];
    __syncthreads();

    // conv3: 32ch x k4 s1 -> [32][19], relu
    for (int idx = tid; idx < 32 * C3OUT; idx += 128) {
        int o = idx / C3OUT, p = idx % C3OUT;
        float acc = c3_b[o];
        #pragma unroll
        for (int c = 0; c < 32; ++c) {
            const float* f = y2 + c * C2OUT + p;
            const float* w = w3 + (o * 32 + c) * 4;
            #pragma unroll
            for (int k = 0; k < 4; ++k) acc += f[k] * w[k];
        }
        y3[o * C3OUT + p] = fmaxf(acc, 0.0f);
    }
    __syncthreads();

    // fc1: [16,608] @ y3, relu — shuffle reduce
    {
        const int wid  = tid >> 5;
        const int lane = tid & 31;
        for (int o = wid; o < 16; o += 4) {
            float a = 0.0f;
            const float* w = fc1_w + o * 608;
            for (int k = lane; k < 608; k += 32) a += y3[k] * w[k];
            #pragma unroll
            for (int s = 16; s > 0; s >>= 1) a += __shfl_xor_sync(0xffffffffu, a, s);
            if (lane == 0) sfc[o] = fmaxf(a + fc1_b[o], 0.0f);
        }
    }
    __syncthreads();

    // fc2: [4,16]
    if (tid < 4) {
        float a = fc2_b[tid];
        #pragma unroll
        for (int k = 0; k < 16; ++k) a += sfc[k] * fc2_w[tid * 16 + k];
        out[(size_t)b * 4 + tid] = a;
    }
}

// ---------------- launch ---------------------------------------------------------
extern "C" void kernel_launch(void* const* d_in, const int* in_sizes, int n_in,
                              void* d_out, int out_size)
{
    const float* x       = (const float*)d_in[0];
    const int*   lengths = (const int*)  d_in[1];
    const float* w_ih    = (const float*)d_in[2];
    const float* w_hh    = (const float*)d_in[3];
    const float* b_ih    = (const float*)d_in[4];
    const float* b_hh    = (const float*)d_in[5];
    const float* w_lin   = (const float*)d_in[6];
    const float* b_lin   = (const float*)d_in[7];
    const float* c1_w    = (const float*)d_in[8];
    const float* c1_b    = (const float*)d_in[9];
    const float* c2_w    = (const float*)d_in[10];
    const float* c2_b    = (const float*)d_in[11];
    const float* c3_w    = (const float*)d_in[12];
    const float* c3_b    = (const float*)d_in[13];
    const float* fc1_w   = (const float*)d_in[14];
    const float* fc1_b   = (const float*)d_in[15];
    const float* fc2_w   = (const float*)d_in[16];
    const float* fc2_b   = (const float*)d_in[17];
    float* out = (float*)d_out;

    // counting sort of sequences by length (load-balances LSTM warps)
    k_zero<<<1, 64>>>();
    k_hist<<<NSEQ / 256, 256>>>(lengths);
    k_scan<<<1, 32>>>();
    k_scatter<<<NSEQ / 256, 256>>>(lengths);

    // masked LSTM + layer summary (2 seqs/thread, packed f32x2)
    k_lstm<<<NPAIR / LSTM_TPB, LSTM_TPB>>>(x, lengths, w_ih, w_hh, b_ih, b_hh,
                                           w_lin, b_lin);

    // conv stack + classifier head
    k_conv<<<NB, 128>>>(c1_w, c1_b, c2_w, c2_b, c3_w, c3_b,
                        fc1_w, fc1_b, fc2_w, fc2_b, out);
}

// round 4
// speedup vs baseline: 1.1423x; 1.1423x over previous
#include <cuda_runtime.h>
#include <cstdint>
#include <math.h>

typedef unsigned long long u64;

#define NB   4096
#define NL   50
#define NT   64
#define NF   3
#define NH   20
#define NG   80
#define NO   16
#define NSEQ (NB*NL)        // 204800
#define TPB  64
#define NQUAD (NSEQ/4)      // 51200 threads
#define NCTA  (NQUAD/TPB)   // 800

// ---------------- device scratch (static; no cudaMalloc) -----------------------
__device__ int   g_hist[64];
__device__ int   g_off[64];
__device__ int   g_order[NSEQ];
__device__ float g_hout[(size_t)NSEQ * NH];   // final h per sequence (16.4 MB)

// ---------------- packed f32x2 helpers ------------------------------------------
__device__ __forceinline__ u64 f2pack(float lo, float hi) {
    u64 r; asm("mov.b64 %0, {%1, %2};" : "=l"(r) : "f"(lo), "f"(hi)); return r;
}
__device__ __forceinline__ void f2unpack(u64 v, float& lo, float& hi) {
    asm("mov.b64 {%0, %1}, %2;" : "=f"(lo), "=f"(hi) : "l"(v));
}
__device__ __forceinline__ u64 ffma2(u64 a, u64 b, u64 c) {
    u64 d; asm("fma.rn.f32x2 %0, %1, %2, %3;" : "=l"(d) : "l"(a), "l"(b), "l"(c)); return d;
}

// accurate fast activations (MUFU.EX2 + MUFU.RCP, ~1e-6 rel err)
__device__ __forceinline__ float fsig(float v) {
    return __fdividef(1.0f, 1.0f + __expf(-v));
}
__device__ __forceinline__ float ftanh(float v) {
    return __fdividef(2.0f, 1.0f + __expf(-2.0f * v)) - 1.0f;
}
__device__ __forceinline__ void lstm_act(float ai, float af, float ag, float ao,
                                         float& c, float& h) {
    float cn = fsig(af) * c + fsig(ai) * ftanh(ag);
    h = fsig(ao) * ftanh(cn);
    c = cn;
}

// ---------------- counting sort by length (DESCENDING buckets) ------------------
__global__ void k_zero() { if (threadIdx.x < 64) g_hist[threadIdx.x] = 0; }

__global__ void k_hist(const int* __restrict__ lengths) {
    __shared__ int sh[64];
    if (threadIdx.x < 64) sh[threadIdx.x] = 0;
    __syncthreads();
    int i = blockIdx.x * 256 + threadIdx.x;
    if (i < NSEQ) atomicAdd(&sh[lengths[i] & 63], 1);
    __syncthreads();
    if (threadIdx.x < 64 && sh[threadIdx.x]) atomicAdd(&g_hist[threadIdx.x], sh[threadIdx.x]);
}
__global__ void k_scan() {
    if (threadIdx.x == 0) {
        int acc = 0;
        #pragma unroll
        for (int i = 63; i >= 0; --i) { int v = g_hist[i]; g_off[i] = acc; acc += v; }
    }
}
__global__ void k_scatter(const int* __restrict__ lengths) {
    __shared__ int sh[64], base[64];
    if (threadIdx.x < 64) sh[threadIdx.x] = 0;
    __syncthreads();
    int i = blockIdx.x * 256 + threadIdx.x, l = 0, r = 0;
    if (i < NSEQ) { l = lengths[i] & 63; r = atomicAdd(&sh[l], 1); }
    __syncthreads();
    if (threadIdx.x < 64) {
        int c = sh[threadIdx.x];
        if (c) base[threadIdx.x] = atomicAdd(&g_off[threadIdx.x], c);
    }
    __syncthreads();
    if (i < NSEQ) g_order[base[l] + r] = i;
}

// ---------------- LSTM: 4 seqs/thread (2 f32x2 packs), shared weight loads ------
// dynamic smem layout (bytes):
#define SO_WHH  0                       // u64[80*20]  12800
#define SO_WIH  12800                   // u64[80*4]    2560 (F padded to 4)
#define SO_B    15360                   // u64[80]       640
#define SO_HNA  16000                   // u64[20*64]  10240
#define SO_HNB  26240                   // u64[20*64]  10240
#define SO_CA   36480                   // u64[20*64]  10240
#define SO_CB   46720                   // u64[20*64]  10240
#define DSMEM_SZ 56960

// dot(h_pack, w_row) accumulated into both packs; one weight load serves both
#define ACC2(accA, accB, rowptr) do {                                          \
    const ulonglong2* wp_ = (const ulonglong2*)(rowptr);                       \
    ulonglong2 w_;                                                             \
    w_ = wp_[0];                                                               \
    accA = ffma2(hA0,  w_.x, accA); accA = ffma2(hA1,  w_.y, accA);            \
    accB = ffma2(hB0,  w_.x, accB); accB = ffma2(hB1,  w_.y, accB);            \
    w_ = wp_[1];                                                               \
    accA = ffma2(hA2,  w_.x, accA); accA = ffma2(hA3,  w_.y, accA);            \
    accB = ffma2(hB2,  w_.x, accB); accB = ffma2(hB3,  w_.y, accB);            \
    w_ = wp_[2];                                                               \
    accA = ffma2(hA4,  w_.x, accA); accA = ffma2(hA5,  w_.y, accA);            \
    accB = ffma2(hB4,  w_.x, accB); accB = ffma2(hB5,  w_.y, accB);            \
    w_ = wp_[3];                                                               \
    accA = ffma2(hA6,  w_.x, accA); accA = ffma2(hA7,  w_.y, accA);            \
    accB = ffma2(hB6,  w_.x, accB); accB = ffma2(hB7,  w_.y, accB);            \
    w_ = wp_[4];                                                               \
    accA = ffma2(hA8,  w_.x, accA); accA = ffma2(hA9,  w_.y, accA);            \
    accB = ffma2(hB8,  w_.x, accB); accB = ffma2(hB9,  w_.y, accB);            \
    w_ = wp_[5];                                                               \
    accA = ffma2(hA10, w_.x, accA); accA = ffma2(hA11, w_.y, accA);            \
    accB = ffma2(hB10, w_.x, accB); accB = ffma2(hB11, w_.y, accB);            \
    w_ = wp_[6];                                                               \
    accA = ffma2(hA12, w_.x, accA); accA = ffma2(hA13, w_.y, accA);            \
    accB = ffma2(hB12, w_.x, accB); accB = ffma2(hB13, w_.y, accB);            \
    w_ = wp_[7];                                                               \
    accA = ffma2(hA14, w_.x, accA); accA = ffma2(hA15, w_.y, accA);            \
    accB = ffma2(hB14, w_.x, accB); accB = ffma2(hB15, w_.y, accB);            \
    w_ = wp_[8];                                                               \
    accA = ffma2(hA16, w_.x, accA); accA = ffma2(hA17, w_.y, accA);            \
    accB = ffma2(hB16, w_.x, accB); accB = ffma2(hB17, w_.y, accB);            \
    w_ = wp_[9];                                                               \
    accA = ffma2(hA18, w_.x, accA); accA = ffma2(hA19, w_.y, accA);            \
    accB = ffma2(hB18, w_.x, accB); accB = ffma2(hB19, w_.y, accB);            \
} while (0)

#define XPROJ2(accA, accB, rowidx) do {                                        \
    const u64* xp_ = sWih + (rowidx) * 4;                                      \
    accA = ffma2(xA0, xp_[0], accA);                                           \
    accA = ffma2(xA1, xp_[1], accA);                                           \
    accA = ffma2(xA2, xp_[2], accA);                                           \
    accB = ffma2(xB0, xp_[0], accB);                                           \
    accB = ffma2(xB1, xp_[1], accB);                                           \
    accB = ffma2(xB2, xp_[2], accB);                                           \
} while (0)

// snapshot: write the SEL (lo_/hi_) lane of h-register set P to dst[0..19]
#define SNAP(P, SEL, dst) do {                                                 \
    float lo_, hi_;                                                            \
    f2unpack(P##0,  lo_, hi_); (dst)[0]  = SEL;                                \
    f2unpack(P##1,  lo_, hi_); (dst)[1]  = SEL;                                \
    f2unpack(P##2,  lo_, hi_); (dst)[2]  = SEL;                                \
    f2unpack(P##3,  lo_, hi_); (dst)[3]  = SEL;                                \
    f2unpack(P##4,  lo_, hi_); (dst)[4]  = SEL;                                \
    f2unpack(P##5,  lo_, hi_); (dst)[5]  = SEL;                                \
    f2unpack(P##6,  lo_, hi_); (dst)[6]  = SEL;                                \
    f2unpack(P##7,  lo_, hi_); (dst)[7]  = SEL;                                \
    f2unpack(P##8,  lo_, hi_); (dst)[8]  = SEL;                                \
    f2unpack(P##9,  lo_, hi_); (dst)[9]  = SEL;                                \
    f2unpack(P##10, lo_, hi_); (dst)[10] = SEL;                                \
    f2unpack(P##11, lo_, hi_); (dst)[11] = SEL;                                \
    f2unpack(P##12, lo_, hi_); (dst)[12] = SEL;                                \
    f2unpack(P##13, lo_, hi_); (dst)[13] = SEL;                                \
    f2unpack(P##14, lo_, hi_); (dst)[14] = SEL;                                \
    f2unpack(P##15, lo_, hi_); (dst)[15] = SEL;                                \
    f2unpack(P##16, lo_, hi_); (dst)[16] = SEL;                                \
    f2unpack(P##17, lo_, hi_); (dst)[17] = SEL;                                \
    f2unpack(P##18, lo_, hi_); (dst)[18] = SEL;                                \
    f2unpack(P##19, lo_, hi_); (dst)[19] = SEL;                                \
} while (0)

__global__ void __launch_bounds__(TPB)
k_lstm(const float* __restrict__ x, const int* __restrict__ lengths,
       const float* __restrict__ w_ih, const float* __restrict__ w_hh,
       const float* __restrict__ b_ih, const float* __restrict__ b_hh)
{
    extern __shared__ __align__(16) char dsm[];
    u64* sWhh = (u64*)(dsm + SO_WHH);
    u64* sWih = (u64*)(dsm + SO_WIH);
    u64* sB   = (u64*)(dsm + SO_B);
    u64* hnA  = (u64*)(dsm + SO_HNA);
    u64* hnB  = (u64*)(dsm + SO_HNB);
    u64* cA   = (u64*)(dsm + SO_CA);
    u64* cB   = (u64*)(dsm + SO_CB);

    const int tid = threadIdx.x;

    for (int i = tid; i < NG * NH; i += TPB) { float w = w_hh[i]; sWhh[i] = f2pack(w, w); }
    for (int i = tid; i < NG * 4; i += TPB) {
        int r = i >> 2, k = i & 3;
        float w = (k < 3) ? w_ih[r * 3 + k] : 0.0f;
        sWih[i] = f2pack(w, w);
    }
    for (int i = tid; i < NG; i += TPB) { float w = b_ih[i] + b_hh[i]; sB[i] = f2pack(w, w); }
    #pragma unroll
    for (int j = 0; j < NH; ++j) { cA[j * TPB + tid] = 0ull; cB[j * TPB + tid] = 0ull; }
    __syncthreads();

    const int qid = blockIdx.x * TPB + tid;
    const int i0 = g_order[4 * qid + 0];
    const int i1 = g_order[4 * qid + 1];
    const int i2 = g_order[4 * qid + 2];
    const int i3 = g_order[4 * qid + 3];
    const int len0 = lengths[i0], len1 = lengths[i1];
    const int len2 = lengths[i2], len3 = lengths[i3];
    const int tmax = max(max(len0, len1), max(len2, len3));

    const float* p0 = x + (size_t)i0 * (NT * NF);
    const float* p1 = x + (size_t)i1 * (NT * NF);
    const float* p2 = x + (size_t)i2 * (NT * NF);
    const float* p3 = x + (size_t)i3 * (NT * NF);

    // h state: 40 NAMED u64 regs (2 packs x 20)
    u64 hA0 = 0, hA1 = 0, hA2 = 0, hA3 = 0, hA4 = 0, hA5 = 0, hA6 = 0, hA7 = 0,
        hA8 = 0, hA9 = 0, hA10 = 0, hA11 = 0, hA12 = 0, hA13 = 0, hA14 = 0,
        hA15 = 0, hA16 = 0, hA17 = 0, hA18 = 0, hA19 = 0;
    u64 hB0 = 0, hB1 = 0, hB2 = 0, hB3 = 0, hB4 = 0, hB5 = 0, hB6 = 0, hB7 = 0,
        hB8 = 0, hB9 = 0, hB10 = 0, hB11 = 0, hB12 = 0, hB13 = 0, hB14 = 0,
        hB15 = 0, hB16 = 0, hB17 = 0, hB18 = 0, hB19 = 0;

    u64 xA0 = 0, xA1 = 0, xA2 = 0, xB0 = 0, xB1 = 0, xB2 = 0;
    if (tmax > 0) {
        xA0 = f2pack(p0[0], p1[0]); xA1 = f2pack(p0[1], p1[1]); xA2 = f2pack(p0[2], p1[2]);
        xB0 = f2pack(p2[0], p3[0]); xB1 = f2pack(p2[1], p3[1]); xB2 = f2pack(p2[2], p3[2]);
    }

    for (int t = 0; t < tmax; ++t) {
        // prefetch next x (row t+1 <= 63 always exists; clamp for safety)
        const int tn = min(t + 1, NT - 1);
        const u64 nA0 = f2pack(p0[3 * tn + 0], p1[3 * tn + 0]);
        const u64 nA1 = f2pack(p0[3 * tn + 1], p1[3 * tn + 1]);
        const u64 nA2 = f2pack(p0[3 * tn + 2], p1[3 * tn + 2]);
        const u64 nB0 = f2pack(p2[3 * tn + 0], p3[3 * tn + 0]);
        const u64 nB1 = f2pack(p2[3 * tn + 1], p3[3 * tn + 1]);
        const u64 nB2 = f2pack(p2[3 * tn + 2], p3[3 * tn + 2]);

        #pragma unroll 1
        for (int j = 0; j < NH; ++j) {
            u64 aiA = sB[j], afA = sB[j + 20], agA = sB[j + 40], aoA = sB[j + 60];
            u64 aiB = aiA,   afB = afA,        agB = agA,        aoB = aoA;

            XPROJ2(aiA, aiB, j);
            XPROJ2(afA, afB, j + 20);
            XPROJ2(agA, agB, j + 40);
            XPROJ2(aoA, aoB, j + 60);

            ACC2(aiA, aiB, sWhh + (j)      * NH);
            ACC2(afA, afB, sWhh + (j + 20) * NH);
            ACC2(agA, agB, sWhh + (j + 40) * NH);
            ACC2(aoA, aoB, sWhh + (j + 60) * NH);

            float i0v, i1v, f0v, f1v, g0v, g1v, o0v, o1v, c0v, c1v, h0v, h1v;

            f2unpack(aiA, i0v, i1v); f2unpack(afA, f0v, f1v);
            f2unpack(agA, g0v, g1v); f2unpack(aoA, o0v, o1v);
            f2unpack(cA[j * TPB + tid], c0v, c1v);
            lstm_act(i0v, f0v, g0v, o0v, c0v, h0v);
            lstm_act(i1v, f1v, g1v, o1v, c1v, h1v);
            cA[j * TPB + tid]  = f2pack(c0v, c1v);
            hnA[j * TPB + tid] = f2pack(h0v, h1v);

            f2unpack(aiB, i0v, i1v); f2unpack(afB, f0v, f1v);
            f2unpack(agB, g0v, g1v); f2unpack(aoB, o0v, o1v);
            f2unpack(cB[j * TPB + tid], c0v, c1v);
            lstm_act(i0v, f0v, g0v, o0v, c0v, h0v);
            lstm_act(i1v, f1v, g1v, o1v, c1v, h1v);
            cB[j * TPB + tid]  = f2pack(c0v, c1v);
            hnB[j * TPB + tid] = f2pack(h0v, h1v);
        }

        // reload h from staging (no masking: snapshot handles per-seq endpoints)
        #define RELOAD(k) hA##k = hnA[(k) * TPB + tid]; hB##k = hnB[(k) * TPB + tid];
        RELOAD(0)  RELOAD(1)  RELOAD(2)  RELOAD(3)  RELOAD(4)
        RELOAD(5)  RELOAD(6)  RELOAD(7)  RELOAD(8)  RELOAD(9)
        RELOAD(10) RELOAD(11) RELOAD(12) RELOAD(13) RELOAD(14)
        RELOAD(15) RELOAD(16) RELOAD(17) RELOAD(18) RELOAD(19)
        #undef RELOAD

        // snapshot final h the moment a sequence completes
        const int tp1 = t + 1;
        if (tp1 == len0) { float* d = g_hout + (size_t)i0 * NH; SNAP(hA, lo_, d); }
        if (tp1 == len1) { float* d = g_hout + (size_t)i1 * NH; SNAP(hA, hi_, d); }
        if (tp1 == len2) { float* d = g_hout + (size_t)i2 * NH; SNAP(hB, lo_, d); }
        if (tp1 == len3) { float* d = g_hout + (size_t)i3 * NH; SNAP(hB, hi_, d); }

        xA0 = nA0; xA1 = nA1; xA2 = nA2;
        xB0 = nB0; xB1 = nB1; xB2 = nB2;
    }
}

// ---------------- conv + FC kernel (now also computes layer summary) ------------
#define C1OUT 46
#define C2OUT 22
#define C3OUT 19

__global__ void __launch_bounds__(128)
k_conv(const int* __restrict__ lengths,
       const float* __restrict__ w_lin, const float* __restrict__ b_lin,
       const float* __restrict__ c1_w, const float* __restrict__ c1_b,
       const float* __restrict__ c2_w, const float* __restrict__ c2_b,
       const float* __restrict__ c3_w, const float* __restrict__ c3_b,
       const float* __restrict__ fc1_w, const float* __restrict__ fc1_b,
       const float* __restrict__ fc2_w, const float* __restrict__ fc2_b,
       float* __restrict__ out)
{
    __shared__ float sbuf[10272];
    __shared__ float sh[NL * NH];     // 1000: h vectors for this batch's 50 layers
    __shared__ float swl[NO * NH];    // 320
    __shared__ float sbl[NO];         // 16
    __shared__ int   slen[NL];        // 50
    __shared__ float sfc[16];

    float* feat = sbuf;               // [16][50] : 800
    float* w1   = sbuf + 800;         // 2560
    float* y1   = sbuf + 3360;        // 1472
    float* w2   = sbuf + 4832;        // 4096
    float* y2   = sbuf + 8928;        // 704
    float* y3   = sbuf + 9632;        // 608
    float* w3   = sbuf;               // reuse [0,4096) after conv2

    const int b   = blockIdx.x;
    const int tid = threadIdx.x;

    // stage h, lengths, summary weights
    if (tid < NL) slen[tid] = lengths[b * NL + tid];
    for (int i = tid; i < NO * NH; i += 128) swl[i] = w_lin[i];
    if (tid < NO) sbl[tid] = b_lin[tid];
    __syncthreads();
    for (int i = tid; i < NL * NH; i += 128) {
        int l = i / NH, k = i % NH;
        sh[i] = (slen[l] > 0) ? g_hout[(size_t)(b * NL + l) * NH + k] : 0.0f;
    }
    for (int i = tid; i < 2560; i += 128) w1[i] = c1_w[i];
    for (int i = tid; i < 4096; i += 128) w2[i] = c2_w[i];
    __syncthreads();

    // layer summary: feat[c][l] = len>0 ? sigmoid(h_l . w_lin[c] + b[c]) : 0
    for (int i = tid; i < NO * NL; i += 128) {
        int c = i / NL, l = i % NL;
        float s = sbl[c];
        #pragma unroll
        for (int k = 0; k < NH; ++k) s += sh[l * NH + k] * swl[c * NH + k];
        feat[c * NL + l] = (slen[l] > 0) ? fsig(s) : 0.0f;
    }
    __syncthreads();

    // conv1: 16ch x k5 s1 -> [32][46], relu
    for (int idx = tid; idx < 32 * C1OUT; idx += 128) {
        int o = idx / C1OUT, ppos = idx % C1OUT;
        float acc = c1_b[o];
        #pragma unroll
        for (int c = 0; c < 16; ++c) {
            const float* f = feat + c * 50 + ppos;
            const float* w = w1 + (o * 16 + c) * 5;
            #pragma unroll
            for (int k = 0; k < 5; ++k) acc += f[k] * w[k];
        }
        y1[o * C1OUT + ppos] = fmaxf(acc, 0.0f);
    }
    __syncthreads();

    // conv2: 32ch x k4 s2 -> [32][22], relu
    for (int idx = tid; idx < 32 * C2OUT; idx += 128) {
        int o = idx / C2OUT, ppos = idx % C2OUT;
        float acc = c2_b[o];
        #pragma unroll
        for (int c = 0; c < 32; ++c) {
            const float* f = y1 + c * C1OUT + 2 * ppos;
            const float* w = w2 + (o * 32 + c) * 4;
            #pragma unroll
            for (int k = 0; k < 4; ++k) acc += f[k] * w[k];
        }
        y2[o * C2OUT + ppos] = fmaxf(acc, 0.0f);
    }
    __syncthreads();

    for (int i = tid; i < 4096; i += 128) w3[i] = c3_w[i];
    __syncthreads();

    // conv3: 32ch x k4 s1 -> [32][19], relu
    for (int idx = tid; idx < 32 * C3OUT; idx += 128) {
        int o = idx / C3OUT, ppos = idx % C3OUT;
        float acc = c3_b[o];
        #pragma unroll
        for (int c = 0; c < 32; ++c) {
            const float* f = y2 + c * C2OUT + ppos;
            const float* w = w3 + (o * 32 + c) * 4;
            #pragma unroll
            for (int k = 0; k < 4; ++k) acc += f[k] * w[k];
        }
        y3[o * C3OUT + ppos] = fmaxf(acc, 0.0f);
    }
    __syncthreads();

    // fc1: [16,608] @ y3, relu — shuffle reduce
    {
        const int wd = tid >> 5, lane = tid & 31;
        for (int o = wd; o < 16; o += 4) {
            float a = 0.0f;
            const float* w = fc1_w + o * 608;
            for (int k = lane; k < 608; k += 32) a += y3[k] * w[k];
            #pragma unroll
            for (int s = 16; s > 0; s >>= 1) a += __shfl_xor_sync(0xffffffffu, a, s);
            if (lane == 0) sfc[o] = fmaxf(a + fc1_b[o], 0.0f);
        }
    }
    __syncthreads();

    // fc2: [4,16]
    if (tid < 4) {
        float a = fc2_b[tid];
        #pragma unroll
        for (int k = 0; k < 16; ++k) a += sfc[k] * fc2_w[tid * 16 + k];
        out[(size_t)b * 4 + tid] = a;
    }
}

// ---------------- launch ----------------------------------------------------------
extern "C" void kernel_launch(void* const* d_in, const int* in_sizes, int n_in,
                              void* d_out, int out_size)
{
    const float* x       = (const float*)d_in[0];
    const int*   lengths = (const int*)  d_in[1];
    const float* w_ih    = (const float*)d_in[2];
    const float* w_hh    = (const float*)d_in[3];
    const float* b_ih    = (const float*)d_in[4];
    const float* b_hh    = (const float*)d_in[5];
    const float* w_lin   = (const float*)d_in[6];
    const float* b_lin   = (const float*)d_in[7];
    const float* c1_w    = (const float*)d_in[8];
    const float* c1_b    = (const float*)d_in[9];
    const float* c2_w    = (const float*)d_in[10];
    const float* c2_b    = (const float*)d_in[11];
    const float* c3_w    = (const float*)d_in[12];
    const float* c3_b    = (const float*)d_in[13];
    const float* fc1_w   = (const float*)d_in[14];
    const float* fc1_b   = (const float*)d_in[15];
    const float* fc2_w   = (const float*)d_in[16];
    const float* fc2_b   = (const float*)d_in[17];
    float* out = (float*)d_out;

    cudaFuncSetAttribute(k_lstm, cudaFuncAttributeMaxDynamicSharedMemorySize, DSMEM_SZ);

    // counting sort, descending length (long sequences scheduled first)
    k_zero<<<1, 64>>>();
    k_hist<<<(NSEQ + 255) / 256, 256>>>(lengths);
    k_scan<<<1, 32>>>();
    k_scatter<<<(NSEQ + 255) / 256, 256>>>(lengths);

    // masked-free LSTM with snapshot-at-length (4 seqs/thread)
    k_lstm<<<NCTA, TPB, DSMEM_SZ>>>(x, lengths, w_ih, w_hh, b_ih, b_hh);

    // layer summary + conv stack + classifier head
    k_conv<<<NB, 128>>>(lengths, w_lin, b_lin, c1_w, c1_b, c2_w, c2_b, c3_w, c3_b,
                        fc1_w, fc1_b, fc2_w, fc2_b, out);
}